// round 10
// baseline (speedup 1.0000x reference)
#include <cuda_runtime.h>
#include <cuda_bf16.h>
#include <math.h>
#include <stdint.h>

#define BB   2
#define SS   2048
#define DD   2048
#define HH   16
#define KVH  8
#define GG   2
#define HD   128
#define SCALE 0.08838834764831845f

typedef __nv_bfloat16 bf16;
typedef __nv_bfloat162 bf162;

// ---------------- persistent scratch ----------------
__device__ float g_q[(size_t)BB * SS * HH  * HD];   // (B,S,H,HD)
__device__ float g_k[(size_t)BB * SS * KVH * HD];   // (B,S,KV,HD)
__device__ float g_v[(size_t)BB * SS * KVH * HD];   // (B,S,KV,HD)
__device__ float g_o[(size_t)BB * SS * HH  * HD];   // (B,S,H,HD)

// ---------------- PTX helpers ----------------
__device__ __forceinline__ uint32_t smaddr(const void* p) {
    return (uint32_t)__cvta_generic_to_shared(p);
}
__device__ __forceinline__ void ldsm_x4(uint32_t* r, uint32_t addr) {
    asm volatile("ldmatrix.sync.aligned.m8n8.x4.shared.b16 {%0,%1,%2,%3}, [%4];"
        : "=r"(r[0]), "=r"(r[1]), "=r"(r[2]), "=r"(r[3]) : "r"(addr));
}
__device__ __forceinline__ void ldsm_x2(uint32_t* r, uint32_t addr) {
    asm volatile("ldmatrix.sync.aligned.m8n8.x2.shared.b16 {%0,%1}, [%2];"
        : "=r"(r[0]), "=r"(r[1]) : "r"(addr));
}
__device__ __forceinline__ void ldsm_x2t(uint32_t* r, uint32_t addr) {
    asm volatile("ldmatrix.sync.aligned.m8n8.x2.trans.shared.b16 {%0,%1}, [%2];"
        : "=r"(r[0]), "=r"(r[1]) : "r"(addr));
}
__device__ __forceinline__ void mma_bf16(float* c, const uint32_t* a, const uint32_t* b) {
    asm volatile(
        "mma.sync.aligned.m16n8k16.row.col.f32.bf16.bf16.f32 "
        "{%0,%1,%2,%3}, {%4,%5,%6,%7}, {%8,%9}, {%0,%1,%2,%3};"
        : "+f"(c[0]), "+f"(c[1]), "+f"(c[2]), "+f"(c[3])
        : "r"(a[0]), "r"(a[1]), "r"(a[2]), "r"(a[3]), "r"(b[0]), "r"(b[1]));
}

// ---------------------------------------------------------------------------
// bf16x3 split GEMM core (unchanged 1609-µs core).
// ---------------------------------------------------------------------------
#define AROW 40
#define BROWN 136
#define QROW 136    // persistent Q row: 128 K-elems + 8 pad (272B stride)

template<bool BTRANS>
__device__ __forceinline__ void gemm_core(
    const float* __restrict__ A, int lda,
    const float* __restrict__ B, int ldb,
    float* __restrict__ C, int ldc, int K, float alpha)
{
    __shared__ __align__(16) __nv_bfloat16 sAh[128 * AROW];
    __shared__ __align__(16) __nv_bfloat16 sAl[128 * AROW];
    __shared__ __align__(16) __nv_bfloat16 sBh[5120];
    __shared__ __align__(16) __nv_bfloat16 sBl[5120];

    const int tid  = threadIdx.x;
    const int lane = tid & 31;
    const int wid  = tid >> 5;
    const int wm   = (wid >> 2) << 6;
    const int wn   = (wid & 3) << 5;

    float acc[4][4][4];
#pragma unroll
    for (int i = 0; i < 4; ++i)
#pragma unroll
        for (int j = 0; j < 4; ++j)
#pragma unroll
            for (int l = 0; l < 4; ++l) acc[i][j][l] = 0.f;

    for (int k0 = 0; k0 < K; k0 += 32) {
        {
            int r = tid >> 3;
            const int c = (tid & 7) << 2;
#pragma unroll
            for (int p = 0; p < 4; ++p, r += 32) {
                float4 v = *(const float4*)(A + (size_t)r * lda + k0 + c);
                __nv_bfloat162 H0 = __floats2bfloat162_rn(v.x, v.y);
                __nv_bfloat162 H1 = __floats2bfloat162_rn(v.z, v.w);
                __nv_bfloat162 L0 = __floats2bfloat162_rn(v.x - __low2float(H0),
                                                          v.y - __high2float(H0));
                __nv_bfloat162 L1 = __floats2bfloat162_rn(v.z - __low2float(H1),
                                                          v.w - __high2float(H1));
                *(__nv_bfloat162*)&sAh[r * AROW + c]     = H0;
                *(__nv_bfloat162*)&sAh[r * AROW + c + 2] = H1;
                *(__nv_bfloat162*)&sAl[r * AROW + c]     = L0;
                *(__nv_bfloat162*)&sAl[r * AROW + c + 2] = L1;
            }
        }
        if (BTRANS) {
            int r = tid >> 3;
            const int c = (tid & 7) << 2;
#pragma unroll
            for (int p = 0; p < 4; ++p, r += 32) {
                float4 v = *(const float4*)(B + (size_t)r * ldb + k0 + c);
                __nv_bfloat162 H0 = __floats2bfloat162_rn(v.x, v.y);
                __nv_bfloat162 H1 = __floats2bfloat162_rn(v.z, v.w);
                __nv_bfloat162 L0 = __floats2bfloat162_rn(v.x - __low2float(H0),
                                                          v.y - __high2float(H0));
                __nv_bfloat162 L1 = __floats2bfloat162_rn(v.z - __low2float(H1),
                                                          v.w - __high2float(H1));
                *(__nv_bfloat162*)&sBh[r * AROW + c]     = H0;
                *(__nv_bfloat162*)&sBh[r * AROW + c + 2] = H1;
                *(__nv_bfloat162*)&sBl[r * AROW + c]     = L0;
                *(__nv_bfloat162*)&sBl[r * AROW + c + 2] = L1;
            }
        } else {
            int r = tid >> 5;
            const int c = (tid & 31) << 2;
#pragma unroll
            for (int p = 0; p < 4; ++p, r += 8) {
                float4 v = *(const float4*)(B + (size_t)(k0 + r) * ldb + c);
                __nv_bfloat162 H0 = __floats2bfloat162_rn(v.x, v.y);
                __nv_bfloat162 H1 = __floats2bfloat162_rn(v.z, v.w);
                __nv_bfloat162 L0 = __floats2bfloat162_rn(v.x - __low2float(H0),
                                                          v.y - __high2float(H0));
                __nv_bfloat162 L1 = __floats2bfloat162_rn(v.z - __low2float(H1),
                                                          v.w - __high2float(H1));
                *(__nv_bfloat162*)&sBh[r * BROWN + c]     = H0;
                *(__nv_bfloat162*)&sBh[r * BROWN + c + 2] = H1;
                *(__nv_bfloat162*)&sBl[r * BROWN + c]     = L0;
                *(__nv_bfloat162*)&sBl[r * BROWN + c + 2] = L1;
            }
        }
        __syncthreads();

#pragma unroll
        for (int ks = 0; ks < 2; ++ks) {
            uint32_t af[4][4];
            uint32_t bh[4][2];
            uint32_t bl[4][2];

            const int arow_off = (lane & 15);
            const int akb = ks * 32 + ((lane >> 4) << 4);

#pragma unroll
            for (int mt = 0; mt < 4; ++mt)
                ldsm_x4(af[mt], smaddr(&sAh[(wm + mt * 16 + arow_off) * AROW]) + akb);

#pragma unroll
            for (int nt = 0; nt < 4; ++nt) {
                if (BTRANS) {
                    uint32_t ad = smaddr(&sBh[(wn + nt * 8 + (lane & 7)) * AROW])
                                + ks * 32 + (((lane >> 3) & 1) << 4);
                    ldsm_x2(bh[nt], ad);
                } else {
                    uint32_t ad = smaddr(&sBh[(ks * 16 + (lane & 15)) * BROWN + wn + nt * 8]);
                    ldsm_x2t(bh[nt], ad);
                }
            }
#pragma unroll
            for (int mt = 0; mt < 4; ++mt)
#pragma unroll
                for (int nt = 0; nt < 4; ++nt)
                    mma_bf16(acc[mt][nt], af[mt], bh[nt]);

#pragma unroll
            for (int nt = 0; nt < 4; ++nt) {
                if (BTRANS) {
                    uint32_t ad = smaddr(&sBl[(wn + nt * 8 + (lane & 7)) * AROW])
                                + ks * 32 + (((lane >> 3) & 1) << 4);
                    ldsm_x2(bl[nt], ad);
                } else {
                    uint32_t ad = smaddr(&sBl[(ks * 16 + (lane & 15)) * BROWN + wn + nt * 8]);
                    ldsm_x2t(bl[nt], ad);
                }
            }
#pragma unroll
            for (int mt = 0; mt < 4; ++mt)
#pragma unroll
                for (int nt = 0; nt < 4; ++nt)
                    mma_bf16(acc[mt][nt], af[mt], bl[nt]);

#pragma unroll
            for (int mt = 0; mt < 4; ++mt)
                ldsm_x4(af[mt], smaddr(&sAl[(wm + mt * 16 + arow_off) * AROW]) + akb);
#pragma unroll
            for (int mt = 0; mt < 4; ++mt)
#pragma unroll
                for (int nt = 0; nt < 4; ++nt)
                    mma_bf16(acc[mt][nt], af[mt], bh[nt]);
        }
        __syncthreads();
    }

#pragma unroll
    for (int mt = 0; mt < 4; ++mt) {
#pragma unroll
        for (int nt = 0; nt < 4; ++nt) {
            int r = wm + mt * 16 + (lane >> 2);
            int c = wn + nt * 8 + ((lane & 3) << 1);
            float2 v0 = make_float2(alpha * acc[mt][nt][0], alpha * acc[mt][nt][1]);
            float2 v1 = make_float2(alpha * acc[mt][nt][2], alpha * acc[mt][nt][3]);
            *(float2*)&C[(size_t)r * ldc + c]       = v0;
            *(float2*)&C[(size_t)(r + 8) * ldc + c] = v1;
        }
    }
}

// ---------------------------------------------------------------------------
// Fused QKV projection (unchanged from R9)
// ---------------------------------------------------------------------------
__global__ __launch_bounds__(256, 2) void qkv_mma(
    const float* __restrict__ x,
    const float* __restrict__ wq, const float* __restrict__ wk,
    const float* __restrict__ wv,
    float* __restrict__ q, float* __restrict__ k, float* __restrict__ v)
{
    const int n0 = blockIdx.x * 128;
    const float* A = x + (size_t)blockIdx.y * 128 * DD;

    if (n0 < HH * HD) {
        const float* B = wq + (size_t)n0 * DD;
        float* C = q + (size_t)blockIdx.y * 128 * (HH * HD) + n0;
        gemm_core<true>(A, DD, B, DD, C, HH * HD, DD, 1.0f);
    } else if (n0 < HH * HD + KVH * HD) {
        const int m = n0 - HH * HD;
        const float* B = wk + (size_t)m * DD;
        float* C = k + (size_t)blockIdx.y * 128 * (KVH * HD) + m;
        gemm_core<true>(A, DD, B, DD, C, KVH * HD, DD, 1.0f);
    } else {
        const int m = n0 - HH * HD - KVH * HD;
        const float* B = wv + (size_t)m * DD;
        float* C = v + (size_t)blockIdx.y * 128 * (KVH * HD) + m;
        gemm_core<true>(A, DD, B, DD, C, KVH * HD, DD, 1.0f);
    }
}

__global__ __launch_bounds__(256, 2) void proj_mma(
    int K, const float* __restrict__ A, int lda,
    const float* __restrict__ B, int ldb, float* __restrict__ C, int ldc)
{
    const float* Ab = A + (size_t)blockIdx.y * 128 * lda;
    const float* Bb = B + (size_t)blockIdx.x * 128 * ldb;
    float* Cb = C + (size_t)blockIdx.y * 128 * ldc + (size_t)blockIdx.x * 128;
    gemm_core<true>(Ab, lda, Bb, ldb, Cb, ldc, K, 1.0f);
}

// ---------------------------------------------------------------------------
// Persistent-Q score kernel. One CTA per (row-block yi, bh); Q split once
// into dynamic smem (88KB, 2 CTAs/SM); loops over <= yi+1 column tiles,
// staging only B per 32-K chunk. Zero-fills columns [span, SS).
// Heavy row-blocks launch first (yi = 15 - blockIdx.x).
// ---------------------------------------------------------------------------
#define SCORE_SMEM (2 * 128 * QROW * 2 + 2 * 128 * AROW * 2)   // 90112 B

__global__ __launch_bounds__(256, 2) void score_persist(
    const float* __restrict__ q, const float* __restrict__ k,
    float* __restrict__ attn)
{
    extern __shared__ __align__(16) bf16 dsm[];
    bf16* sQh = dsm;
    bf16* sQl = dsm + 128 * QROW;
    bf16* sBh = dsm + 2 * 128 * QROW;
    bf16* sBl = dsm + 2 * 128 * QROW + 128 * AROW;

    const int yi = 15 - (int)blockIdx.x;       // heavy first
    const int bh = blockIdx.y;
    const int h = bh % HH, b = bh / HH, kv = h / GG;
    const float* Aq = q + ((size_t)b * SS * HH + h) * HD
                        + (size_t)yi * 128 * (HH * HD);
    const float* Bk = k + ((size_t)b * SS * KVH + kv) * HD;
    float* Cbh = attn + (size_t)bh * SS * SS + (size_t)yi * 128 * SS;

    const int tid  = threadIdx.x;
    const int lane = tid & 31;
    const int wid  = tid >> 5;
    const int wm   = (wid >> 2) << 6;
    const int wn   = (wid & 3) << 5;
    const int lda  = HH * HD;
    const int ldb  = KVH * HD;
    const int span = (yi + 1) * 128;

    // zero-fill [span, SS) columns of this row block
    {
        const float4 z = make_float4(0.f, 0.f, 0.f, 0.f);
        for (int r = wid; r < 128; r += 8)
            for (int c = span + (lane << 2); c < SS; c += 128)
                *(float4*)&Cbh[(size_t)r * SS + c] = z;
    }

    // stage Q once: 128 rows x 128 K, hi/lo split
    for (int t = tid; t < 4096; t += 256) {
        const int r = t >> 5, c = (t & 31) << 2;
        float4 v = *(const float4*)(Aq + (size_t)r * lda + c);
        bf162 H0 = __floats2bfloat162_rn(v.x, v.y);
        bf162 H1 = __floats2bfloat162_rn(v.z, v.w);
        bf162 L0 = __floats2bfloat162_rn(v.x - __low2float(H0), v.y - __high2float(H0));
        bf162 L1 = __floats2bfloat162_rn(v.z - __low2float(H1), v.w - __high2float(H1));
        *(bf162*)&sQh[r * QROW + c]     = H0;
        *(bf162*)&sQh[r * QROW + c + 2] = H1;
        *(bf162*)&sQl[r * QROW + c]     = L0;
        *(bf162*)&sQl[r * QROW + c + 2] = L1;
    }
    __syncthreads();

    for (int xt = 0; xt <= yi; ++xt) {
        const float* Bt = Bk + (size_t)xt * 128 * ldb;
        float acc[4][4][4];
#pragma unroll
        for (int i = 0; i < 4; ++i)
#pragma unroll
            for (int j = 0; j < 4; ++j)
#pragma unroll
                for (int l = 0; l < 4; ++l) acc[i][j][l] = 0.f;

#pragma unroll
        for (int ch = 0; ch < 4; ++ch) {
            // stage B chunk (128 rows x 32 K), hi/lo split
            {
                int r = tid >> 3;
                const int c = (tid & 7) << 2;
#pragma unroll
                for (int p = 0; p < 4; ++p, r += 32) {
                    float4 v = *(const float4*)(Bt + (size_t)r * ldb + ch * 32 + c);
                    bf162 H0 = __floats2bfloat162_rn(v.x, v.y);
                    bf162 H1 = __floats2bfloat162_rn(v.z, v.w);
                    bf162 L0 = __floats2bfloat162_rn(v.x - __low2float(H0),
                                                     v.y - __high2float(H0));
                    bf162 L1 = __floats2bfloat162_rn(v.z - __low2float(H1),
                                                     v.w - __high2float(H1));
                    *(bf162*)&sBh[r * AROW + c]     = H0;
                    *(bf162*)&sBh[r * AROW + c + 2] = H1;
                    *(bf162*)&sBl[r * AROW + c]     = L0;
                    *(bf162*)&sBl[r * AROW + c + 2] = L1;
                }
            }
            __syncthreads();

#pragma unroll
            for (int ks = 0; ks < 2; ++ks) {
                uint32_t af[4][4], bh[4][2], bl[4][2];
                const int arow_off = (lane & 15);
                const int qkb = ch * 64 + ks * 32 + ((lane >> 4) << 4);
                const int bkb = ks * 32 + (((lane >> 3) & 1) << 4);

#pragma unroll
                for (int mt = 0; mt < 4; ++mt)
                    ldsm_x4(af[mt], smaddr(&sQh[(wm + mt * 16 + arow_off) * QROW]) + qkb);
#pragma unroll
                for (int nt = 0; nt < 4; ++nt)
                    ldsm_x2(bh[nt], smaddr(&sBh[(wn + nt * 8 + (lane & 7)) * AROW]) + bkb);
#pragma unroll
                for (int mt = 0; mt < 4; ++mt)
#pragma unroll
                    for (int nt = 0; nt < 4; ++nt) mma_bf16(acc[mt][nt], af[mt], bh[nt]);

#pragma unroll
                for (int nt = 0; nt < 4; ++nt)
                    ldsm_x2(bl[nt], smaddr(&sBl[(wn + nt * 8 + (lane & 7)) * AROW]) + bkb);
#pragma unroll
                for (int mt = 0; mt < 4; ++mt)
#pragma unroll
                    for (int nt = 0; nt < 4; ++nt) mma_bf16(acc[mt][nt], af[mt], bl[nt]);

#pragma unroll
                for (int mt = 0; mt < 4; ++mt)
                    ldsm_x4(af[mt], smaddr(&sQl[(wm + mt * 16 + arow_off) * QROW]) + qkb);
#pragma unroll
                for (int mt = 0; mt < 4; ++mt)
#pragma unroll
                    for (int nt = 0; nt < 4; ++nt) mma_bf16(acc[mt][nt], af[mt], bh[nt]);
            }
            __syncthreads();
        }

        float* C = Cbh + xt * 128;
#pragma unroll
        for (int mt = 0; mt < 4; ++mt) {
#pragma unroll
            for (int nt = 0; nt < 4; ++nt) {
                int r = wm + mt * 16 + (lane >> 2);
                int c = wn + nt * 8 + ((lane & 3) << 1);
                float2 v0 = make_float2(SCALE * acc[mt][nt][0], SCALE * acc[mt][nt][1]);
                float2 v1 = make_float2(SCALE * acc[mt][nt][2], SCALE * acc[mt][nt][3]);
                *(float2*)&C[(size_t)r * SS + c]       = v0;
                *(float2*)&C[(size_t)(r + 8) * SS + c] = v1;
            }
        }
    }
}

// AV (heavy-first K ordering)
__global__ __launch_bounds__(256, 2) void av_mma(
    const float* __restrict__ attn, const float* __restrict__ v,
    float* __restrict__ o)
{
    const int ry = 15 - (int)blockIdx.y;       // heavy first
    const int bh = blockIdx.z;
    const int h = bh % HH, b = bh / HH, kv = h / GG;
    const float* A = attn + (size_t)bh * SS * SS + (size_t)ry * 128 * SS;
    const float* B = v + ((size_t)b * SS * KVH + kv) * HD;
    float* C = o + ((size_t)b * SS * HH + h) * HD + (size_t)ry * 128 * (HH * HD);
    const int K = (ry + 1) * 128;
    gemm_core<false>(A, SS, B, KVH * HD, C, HH * HD, K, 1.0f);
}

// ---------------------------------------------------------------------------
// Fused RMSNorm + RoPE for BOTH Q and K in one launch.
// ---------------------------------------------------------------------------
__global__ __launch_bounds__(128) void normrope_all(
    float* __restrict__ qd, float* __restrict__ kd,
    const float* __restrict__ qw, const float* __restrict__ kw,
    const float* __restrict__ cosb, const float* __restrict__ sinb)
{
    const int HT = HH + KVH;   // 24
    const int idx = blockIdx.x;
    const int hh = idx % HT;
    const int s = (idx / HT) % SS;
    const int b = idx / (HT * SS);
    const int t = threadIdx.x;

    float* ptr;
    const float* w;
    if (hh < HH) { ptr = qd + (((size_t)b * SS + s) * HH + hh) * HD; w = qw; }
    else         { ptr = kd + (((size_t)b * SS + s) * KVH + (hh - HH)) * HD; w = kw; }

    float v = ptr[t];
    float ss = v * v;
#pragma unroll
    for (int o = 16; o; o >>= 1) ss += __shfl_xor_sync(0xffffffffu, ss, o);

    __shared__ float ws[4];
    __shared__ float sh[128];
    const int lane = t & 31, wid = t >> 5;
    if (lane == 0) ws[wid] = ss;
    __syncthreads();
    float var = (ws[0] + ws[1] + ws[2] + ws[3]) * (1.0f / HD);
    float xn = v * rsqrtf(var + 1e-6f) * w[t];
    sh[t] = xn;
    __syncthreads();
    float rot = (t < 64) ? -sh[t + 64] : sh[t - 64];

    const float* cp = cosb + ((size_t)b * SS + s) * HD;
    const float* sp = sinb + ((size_t)b * SS + s) * HD;
    ptr[t] = xn * cp[t] + rot * sp[t];
}

// ---------------------------------------------------------------------------
// Row softmax (causal), span-only writes, warp-shuffle reductions.
// ---------------------------------------------------------------------------
__global__ __launch_bounds__(256) void softmax_kernel(float* __restrict__ attn)
{
    __shared__ float buf[SS];
    __shared__ float redm[8];
    __shared__ float reds[8];
    const int row = blockIdx.x;
    const int qi = row & (SS - 1);
    const int valid = qi + 1;
    const int span = ((qi >> 7) + 1) << 7;
    float* base = attn + (size_t)row * SS;
    const int tid = threadIdx.x;
    const int lane = tid & 31, wrp = tid >> 5;

    float m = -1e30f;
    for (int t = tid * 4; t < span; t += 1024) {
        float4 v = *(const float4*)(base + t);
        v.x = (t + 0 < valid) ? v.x : -1e30f;
        v.y = (t + 1 < valid) ? v.y : -1e30f;
        v.z = (t + 2 < valid) ? v.z : -1e30f;
        v.w = (t + 3 < valid) ? v.w : -1e30f;
        *(float4*)(buf + t) = v;
        m = fmaxf(m, fmaxf(fmaxf(v.x, v.y), fmaxf(v.z, v.w)));
    }
#pragma unroll
    for (int o = 16; o; o >>= 1) m = fmaxf(m, __shfl_xor_sync(0xffffffffu, m, o));
    if (lane == 0) redm[wrp] = m;
    __syncthreads();
    float mx = redm[0];
#pragma unroll
    for (int i = 1; i < 8; ++i) mx = fmaxf(mx, redm[i]);

    float sum = 0.f;
    for (int t = tid * 4; t < span; t += 1024) {
        float4 v = *(const float4*)(buf + t);
        v.x = expf(v.x - mx); v.y = expf(v.y - mx);
        v.z = expf(v.z - mx); v.w = expf(v.w - mx);
        *(float4*)(buf + t) = v;
        sum += v.x + v.y + v.z + v.w;
    }
#pragma unroll
    for (int o = 16; o; o >>= 1) sum += __shfl_xor_sync(0xffffffffu, sum, o);
    if (lane == 0) reds[wrp] = sum;
    __syncthreads();
    float tot = reds[0] + reds[1] + reds[2] + reds[3]
              + reds[4] + reds[5] + reds[6] + reds[7];
    const float inv = 1.0f / tot;

    for (int t = tid * 4; t < span; t += 1024) {
        float4 v = *(const float4*)(buf + t);
        v.x *= inv; v.y *= inv; v.z *= inv; v.w *= inv;
        *(float4*)(base + t) = v;
    }
}

// ---------------- launch ----------------
extern "C" void kernel_launch(void* const* d_in, const int* in_sizes, int n_in,
                              void* d_out, int out_size)
{
    const float* x    = (const float*)d_in[0];
    const float* cosb = (const float*)d_in[1];
    const float* sinb = (const float*)d_in[2];
    const float* wq   = (const float*)d_in[4];
    const float* wk   = (const float*)d_in[5];
    const float* wv   = (const float*)d_in[6];
    const float* wo   = (const float*)d_in[7];
    const float* qw   = (const float*)d_in[8];
    const float* kw   = (const float*)d_in[9];

    float* out  = (float*)d_out;                    // (B,S,H*HD)
    float* attn = out + (size_t)BB * SS * HH * HD;  // (B,H,S,S)

    float *pq, *pk, *pv, *po;
    cudaGetSymbolAddress((void**)&pq, g_q);
    cudaGetSymbolAddress((void**)&pk, g_k);
    cudaGetSymbolAddress((void**)&pv, g_v);
    cudaGetSymbolAddress((void**)&po, g_o);

    cudaFuncSetAttribute(score_persist,
                         cudaFuncAttributeMaxDynamicSharedMemorySize, SCORE_SMEM);

    const int BS = BB * SS;   // 4096
    dim3 blk(256);

    // Fused QKV projection
    qkv_mma<<<dim3(32, BS / 128), blk>>>(x, wq, wk, wv, pq, pk, pv);

    // RMSNorm + RoPE (Q and K in one launch)
    normrope_all<<<BB * SS * (HH + KVH), 128>>>(pq, pk, qw, kw, cosb, sinb);

    // Scores (persistent-Q, zero-fill integrated, heavy-first)
    score_persist<<<dim3(16, BB * HH), blk, SCORE_SMEM>>>(pq, pk, attn);

    // Softmax (span-only), AV (heavy-first)
    softmax_kernel<<<BB * HH * SS, 256>>>(attn);
    av_mma<<<dim3(1, 16, BB * HH), blk>>>(attn, pv, po);

    // Output projection
    proj_mma<<<dim3(DD / 128, BS / 128), blk>>>(
        HH * HD, po, HH * HD, wo, HH * HD, out, DD);
}